// round 7
// baseline (speedup 1.0000x reference)
#include <cuda_runtime.h>
#include <cstdint>
#include <math_constants.h>

#define IN_DIM   128
#define HID      64
#define G_MAX    8192
#define CHUNK    128
#define THREADS  256
#define XT       132   // xs_t row stride (floats) -> conflict-free ld/st phases

// Shared memory layout (bytes)
#define XS_BYTES    (IN_DIM * XT * 4)                // 67584: xs_t[dim][node]
#define WS_OFF      XS_BYTES                          // W1 as f32 pairs [k][HID/2]
#define WS_U64      (IN_DIM * (HID / 2))              // 4096 u64 = 32768 B
#define B1_OFF      (WS_OFF + WS_U64 * 8)             // 100352
#define W2_OFF      (B1_OFF + HID * 4)                // 100608
#define ES_OFF      (W2_OFF + HID * 4)                // 100864 (128 floats)
#define ACC2_OFF    (ES_OFF + CHUNK * 4)              // 101376 (128 floats)
#define RED_OFF     (ACC2_OFF + IN_DIM * 4)           // 101888 (8 floats)
#define SMEM_TOTAL  (RED_OFF + 8 * 4)                 // ~99.5 KB -> 2 CTAs/SM

__device__ int g_seg_start[G_MAX + 1];

// ---------------------------------------------------------------------------
// Kernel 1: segment offsets from sorted batch (int32 view; inline i64 detect).
// ---------------------------------------------------------------------------
__global__ void seg_offsets_kernel(const int* __restrict__ b32, int n, int G)
{
    int i = blockIdx.x * blockDim.x + threadIdx.x;
    if (i > n) return;
    const int s = (b32[(n / 2) | 1] == 0) ? 2 : 1;   // int64 -> stride 2 (low word)
    int cur  = (i < n) ? b32[(size_t)i * s]       : G;
    int prev = (i > 0) ? b32[(size_t)(i - 1) * s] : -1;
    cur  = min(max(cur,  -1), G);
    prev = min(max(prev, -1), G);
    for (int g = prev + 1; g <= cur; ++g)
        g_seg_start[g] = i;
}

// packed f32x2 FMA — PTX-only, 2x tput vs scalar FFMA
__device__ __forceinline__ unsigned long long ffma2(unsigned long long a,
                                                    unsigned long long b,
                                                    unsigned long long c)
{
    unsigned long long d;
    asm("fma.rn.f32x2 %0, %1, %2, %3;" : "=l"(d) : "l"(a), "l"(b), "l"(c));
    return d;
}

__device__ __forceinline__ unsigned long long pack_dup(float x)
{
    unsigned long long r;
    uint32_t xu = __float_as_uint(x);
    asm("mov.b64 %0, {%1, %1};" : "=l"(r) : "r"(xu));
    return r;
}

__device__ __forceinline__ void unpack2(unsigned long long v, float& lo, float& hi)
{
    uint32_t l, h;
    asm("mov.b64 {%0, %1}, %2;" : "=r"(l), "=r"(h) : "l"(v));
    lo = __uint_as_float(l);
    hi = __uint_as_float(h);
}

// ---------------------------------------------------------------------------
// Kernel 2: fused gate-MLP (register-tiled) + online softmax + pooling.
// One CTA per graph, 256 threads. xs staged TRANSPOSED: xs_t[dim][node].
// MLP tile: thread = (ngrp 0..31, hgrp 0..7) computes 4 nodes x 8 hid.
// ---------------------------------------------------------------------------
__global__ __launch_bounds__(THREADS, 2)
void attn_pool_kernel(const float* __restrict__ x,
                      const float* __restrict__ W1,
                      const float* __restrict__ b1,
                      const float* __restrict__ W2,
                      const float* __restrict__ b2,
                      float* __restrict__ out)
{
    extern __shared__ char smem[];
    float*              xs   = (float*)smem;                         // [128][XT]
    unsigned long long* ws   = (unsigned long long*)(smem + WS_OFF);
    float*              b1s  = (float*)(smem + B1_OFF);
    float*              w2s  = (float*)(smem + W2_OFF);
    float*              es   = (float*)(smem + ES_OFF);              // gates / e
    float*              acc2 = (float*)(smem + ACC2_OFF);
    float*              red  = (float*)(smem + RED_OFF);

    const int tid  = threadIdx.x;
    const int lane = tid & 31;
    const int wid  = tid >> 5;       // 0..7
    const int hgrp = tid & 7;        // hid group: hid = hgrp*8 + j
    const int ngrp = tid >> 3;       // node group: node = ngrp*4 + i  (0..31)
    const int dim  = tid & (IN_DIM - 1);
    const int half = tid >> 7;       // 0/1: node-range half for load/pool
    const int g    = blockIdx.x;

    const int start = g_seg_start[g];
    const int end   = g_seg_start[g + 1];

    // Stage weights (reused across chunks)
    {
        const unsigned long long* w1u = (const unsigned long long*)W1;
        for (int i = tid; i < WS_U64; i += THREADS) ws[i] = w1u[i];
        if (tid < HID) { b1s[tid] = b1[tid]; w2s[tid] = W2[tid]; }
    }
    const float b2v = b2[0];

    float m_run = -CUDART_INF_F;
    float s_run = 0.f;
    float acc   = 0.f;   // dim `dim`, node-half `half`

    for (int cs = start; cs < end; cs += CHUNK) {
        const int c = min(CHUNK, end - cs);
        __syncthreads();   // xs/es from previous chunk fully consumed

        // ---- load x chunk transposed. thread: dim, node-half; 16 quads each.
        // LDGs coalesce across lanes (consecutive dims of one node);
        // STS.128 conflict-free (phase lanes hit distinct banks via XT=132).
        {
            const float* xb = x + (size_t)cs * IN_DIM + dim;
            float* dst = xs + dim * XT + half * (CHUNK / 2);
            if (c == CHUNK) {                       // fast path: no guards
                #pragma unroll 4
                for (int q = 0; q < CHUNK / 8; ++q) {
                    const int n0 = half * (CHUNK / 2) + 4 * q;
                    float4 v;
                    v.x = xb[(size_t)(n0 + 0) * IN_DIM];
                    v.y = xb[(size_t)(n0 + 1) * IN_DIM];
                    v.z = xb[(size_t)(n0 + 2) * IN_DIM];
                    v.w = xb[(size_t)(n0 + 3) * IN_DIM];
                    *(float4*)(dst + 4 * q) = v;
                }
            } else {                                // tail: zero-pad
                #pragma unroll 4
                for (int q = 0; q < CHUNK / 8; ++q) {
                    const int n0 = half * (CHUNK / 2) + 4 * q;
                    float4 v;
                    v.x = (n0 + 0 < c) ? xb[(size_t)(n0 + 0) * IN_DIM] : 0.f;
                    v.y = (n0 + 1 < c) ? xb[(size_t)(n0 + 1) * IN_DIM] : 0.f;
                    v.z = (n0 + 2 < c) ? xb[(size_t)(n0 + 2) * IN_DIM] : 0.f;
                    v.w = (n0 + 3 < c) ? xb[(size_t)(n0 + 3) * IN_DIM] : 0.f;
                    *(float4*)(dst + 4 * q) = v;
                }
            }
        }
        __syncthreads();

        // ---- gate MLP: 4 nodes x 8 hid register tile, FFMA2 accumulators
        {
            unsigned long long h[16];             // [node i][hid pair p] = h[i*4+p]
            const unsigned long long zero2 = pack_dup(0.f);
            #pragma unroll
            for (int t = 0; t < 16; ++t) h[t] = zero2;

            const float*              xrow = xs + ngrp * 4;        // + k*XT
            const unsigned long long* wrow = ws + hgrp * 4;        // + k*(HID/2)

            #pragma unroll 2
            for (int k = 0; k < IN_DIM; ++k) {
                const float4 xa = *(const float4*)(xrow + k * XT);
                const ulonglong2 w0  = *(const ulonglong2*)(wrow + k * (HID / 2));
                const ulonglong2 w1v = *(const ulonglong2*)(wrow + k * (HID / 2) + 2);
                unsigned long long xd[4];
                xd[0] = pack_dup(xa.x); xd[1] = pack_dup(xa.y);
                xd[2] = pack_dup(xa.z); xd[3] = pack_dup(xa.w);
                #pragma unroll
                for (int i = 0; i < 4; ++i) {
                    h[i * 4 + 0] = ffma2(xd[i], w0.x,  h[i * 4 + 0]);
                    h[i * 4 + 1] = ffma2(xd[i], w0.y,  h[i * 4 + 1]);
                    h[i * 4 + 2] = ffma2(xd[i], w1v.x, h[i * 4 + 2]);
                    h[i * 4 + 3] = ffma2(xd[i], w1v.y, h[i * 4 + 3]);
                }
            }

            // epilogue: relu + W2 partial per node, reduce across 8 hgrp lanes
            float partial[4];
            #pragma unroll
            for (int i = 0; i < 4; ++i) {
                float p = 0.f;
                #pragma unroll
                for (int pp = 0; pp < 4; ++pp) {
                    float lo, hi;
                    unpack2(h[i * 4 + pp], lo, hi);
                    const int j = hgrp * 8 + 2 * pp;
                    lo = fmaxf(lo + b1s[j], 0.f);
                    hi = fmaxf(hi + b1s[j + 1], 0.f);
                    p = fmaf(lo, w2s[j], p);
                    p = fmaf(hi, w2s[j + 1], p);
                }
                partial[i] = p;
            }
            #pragma unroll
            for (int off = 1; off < 8; off <<= 1)
                #pragma unroll
                for (int i = 0; i < 4; ++i)
                    partial[i] += __shfl_xor_sync(0xffffffffu, partial[i], off, 8);

            if (hgrp < 4) {
                const int node = ngrp * 4 + hgrp;
                es[node] = (node < c) ? (partial[hgrp] + b2v) : -CUDART_INF_F;
            }
        }
        __syncthreads();

        // ---- softmax (all 256 threads track m_run/s_run consistently)
        const float gate = es[tid & (CHUNK - 1)];
        float v = gate;
        #pragma unroll
        for (int o = 16; o; o >>= 1) v = fmaxf(v, __shfl_xor_sync(0xffffffffu, v, o));
        if (lane == 0) red[wid] = v;
        __syncthreads();
        float cmax = red[0];
        #pragma unroll
        for (int w = 1; w < THREADS / 32; ++w) cmax = fmaxf(cmax, red[w]);
        const float m_new = fmaxf(m_run, cmax);
        const float resc  = expf(m_run - m_new);   // first chunk: exp(-inf) = 0

        const float e = expf(gate - m_new);        // pad gates -inf -> e = 0
        __syncthreads();   // gates + red fully read before overwrite
        if (tid < CHUNK) es[tid] = e;
        float sv = (tid < CHUNK) ? e : 0.f;        // avoid double-count
        #pragma unroll
        for (int o = 16; o; o >>= 1) sv += __shfl_xor_sync(0xffffffffu, sv, o);
        if (lane == 0) red[wid] = sv;
        __syncthreads();
        float csum = red[0];
        #pragma unroll
        for (int w = 1; w < THREADS / 32; ++w) csum += red[w];

        s_run = s_run * resc + csum;
        m_run = m_new;

        // ---- weighted accumulate: thread (dim, half) sums its 64 nodes.
        acc *= resc;
        {
            const float4* e4   = (const float4*)es;
            const float*  xrow = xs + dim * XT + half * (CHUNK / 2);
            #pragma unroll 4
            for (int n4 = 0; n4 < CHUNK / 8; ++n4) {
                const float4 ev = e4[half * (CHUNK / 8) + n4];
                const float4 xv = *(const float4*)(xrow + 4 * n4);
                acc = fmaf(ev.x, xv.x, acc);
                acc = fmaf(ev.y, xv.y, acc);
                acc = fmaf(ev.z, xv.z, acc);
                acc = fmaf(ev.w, xv.w, acc);
            }
        }
    }

    // combine the two node-half partials through smem
    __syncthreads();
    if (half == 1) acc2[dim] = acc;
    __syncthreads();
    if (half == 0)
        out[(size_t)g * IN_DIM + dim] =
            (end > start) ? (acc + acc2[dim]) / s_run : 0.f;
}

// ---------------------------------------------------------------------------
extern "C" void kernel_launch(void* const* d_in, const int* in_sizes, int n_in,
                              void* d_out, int out_size)
{
    const float* x   = (const float*)d_in[0];
    const int*   b32 = (const int*)d_in[1];   // int32 view: safe for i32/i64
    const float* W1  = (const float*)d_in[2];
    const float* b1  = (const float*)d_in[3];
    const float* W2  = (const float*)d_in[4];
    const float* b2  = (const float*)d_in[5];
    float*       out = (float*)d_out;

    const int N = in_sizes[0] / IN_DIM;
    int G = out_size / IN_DIM;
    if (G > G_MAX) G = G_MAX;

    seg_offsets_kernel<<<(N + 1 + 255) / 256, 256>>>(b32, N, G);

    cudaFuncSetAttribute(attn_pool_kernel,
                         cudaFuncAttributeMaxDynamicSharedMemorySize, SMEM_TOTAL);
    attn_pool_kernel<<<G, THREADS, SMEM_TOTAL>>>(x, W1, b1, W2, b2, out);
}

// round 9
// speedup vs baseline: 1.4607x; 1.4607x over previous
#include <cuda_runtime.h>
#include <cuda_bf16.h>
#include <cstdint>
#include <math_constants.h>

#define IN_DIM   128
#define HID      64
#define G_MAX    8192
#define CHUNK    128
#define THREADS  128
#define KP       136        // bf16 row stride: 272 B = 17*16B -> ldmatrix conflict-free

// ---- SMEM layout (bytes); all tile bases 16B-aligned
#define XH_OFF    0                         // x hi  [128 nodes][KP] bf16 = 34816
#define XL_OFF    34816                     // x lo
#define WH_OFF    69632                     // W1^T hi [64 n][KP] bf16 = 17408
#define WL_OFF    87040                     // W1^T lo
#define B1S_OFF   104448                    // 64 f32
#define W2S_OFF   104704                    // 64 f32
#define ES_OFF    104960                    // 128 f32 (gates, then exp weights)
#define ACC2_OFF  105472                    // 128 f32 (pool half-combine)
#define RED_OFF   105984                    // 4 f32 + pad
#define SMEM_TOTAL 106048                   // x2 = 212 KB <= 228 KB -> 2 CTAs/SM

__device__ int g_seg_start[G_MAX + 1];

// ---------------------------------------------------------------------------
// Kernel 1: segment offsets from sorted batch (int32 view; inline i64 detect).
// ---------------------------------------------------------------------------
__global__ void seg_offsets_kernel(const int* __restrict__ b32, int n, int G)
{
    int i = blockIdx.x * blockDim.x + threadIdx.x;
    if (i > n) return;
    const int s = (b32[(n / 2) | 1] == 0) ? 2 : 1;   // int64 -> stride 2 (low word)
    int cur  = (i < n) ? b32[(size_t)i * s]       : G;
    int prev = (i > 0) ? b32[(size_t)(i - 1) * s] : -1;
    cur  = min(max(cur,  -1), G);
    prev = min(max(prev, -1), G);
    for (int g = prev + 1; g <= cur; ++g)
        g_seg_start[g] = i;
}

// ---------------------------------------------------------------------------
// baseline-feature tensor ops (sm_80+, legal at compute_103)
// ---------------------------------------------------------------------------
__device__ __forceinline__ uint32_t smem_u32(const void* p)
{
    uint32_t a;
    asm("{ .reg .u64 t; cvta.to.shared.u64 t, %1; cvt.u32.u64 %0, t; }"
        : "=r"(a) : "l"(p));
    return a;
}

__device__ __forceinline__ void ldmx4(uint32_t addr, uint32_t* r)
{
    asm volatile("ldmatrix.sync.aligned.m8n8.x4.shared.b16 {%0,%1,%2,%3}, [%4];"
                 : "=r"(r[0]), "=r"(r[1]), "=r"(r[2]), "=r"(r[3]) : "r"(addr));
}

__device__ __forceinline__ void mma16816(float* c, const uint32_t* a,
                                         const uint32_t* b)
{
    asm volatile("mma.sync.aligned.m16n8k16.row.col.f32.bf16.bf16.f32 "
                 "{%0,%1,%2,%3}, {%4,%5,%6,%7}, {%8,%9}, {%0,%1,%2,%3};"
                 : "+f"(c[0]), "+f"(c[1]), "+f"(c[2]), "+f"(c[3])
                 : "r"(a[0]), "r"(a[1]), "r"(a[2]), "r"(a[3]),
                   "r"(b[0]), "r"(b[1]));
}

__device__ __forceinline__ uint32_t pack_bf16x2(float v0, float v1,
                                                uint32_t& lo_out)
{
    const __nv_bfloat16 h0 = __float2bfloat16(v0);
    const __nv_bfloat16 h1 = __float2bfloat16(v1);
    const __nv_bfloat16 l0 = __float2bfloat16(v0 - __bfloat162float(h0));
    const __nv_bfloat16 l1 = __float2bfloat16(v1 - __bfloat162float(h1));
    lo_out = ((uint32_t)__bfloat16_as_ushort(l1) << 16) |
              (uint32_t)__bfloat16_as_ushort(l0);
    return ((uint32_t)__bfloat16_as_ushort(h1) << 16) |
            (uint32_t)__bfloat16_as_ushort(h0);
}

// ---------------------------------------------------------------------------
// Kernel 2: fused gate-MLP (mma.sync bf16 hi/lo split) + softmax + pooling.
// One CTA per graph, 128 threads (4 warps). Per chunk:
//   stage x -> bf16 hi/lo [node][k];  D = Ah*Bh + Ah*Bl + Al*Bh (fp32 accum);
//   warp w owns nodes 32w..32w+31 (2 m16 tiles) x all 64 hid (8 n8 tiles);
//   epilogue relu+W2 -> gate/node; online softmax; pool from xh+xl.
// ---------------------------------------------------------------------------
__global__ __launch_bounds__(THREADS, 2)
void attn_pool_kernel(const float* __restrict__ x,
                      const float* __restrict__ W1,
                      const float* __restrict__ b1,
                      const float* __restrict__ W2,
                      const float* __restrict__ b2,
                      float* __restrict__ out)
{
    extern __shared__ char smem[];
    float* b1s  = (float*)(smem + B1S_OFF);
    float* w2s  = (float*)(smem + W2S_OFF);
    float* es   = (float*)(smem + ES_OFF);
    float* acc2 = (float*)(smem + ACC2_OFF);
    float* red  = (float*)(smem + RED_OFF);

    const uint32_t sb = smem_u32(smem);

    const int tid  = threadIdx.x;
    const int lane = tid & 31;
    const int wid  = tid >> 5;
    const int g    = blockIdx.x;

    const int start = g_seg_start[g];
    const int end   = g_seg_start[g + 1];

    // ---- stage W1^T hi/lo [n][k] (one-time; matches col-major B fragment)
    for (int e = tid; e < HID * IN_DIM; e += THREADS) {
        const int n = e & (HID - 1);
        const int k = e >> 6;
        const float v = W1[k * HID + n];
        const __nv_bfloat16 h = __float2bfloat16(v);
        const __nv_bfloat16 l = __float2bfloat16(v - __bfloat162float(h));
        *(__nv_bfloat16*)(smem + WH_OFF + (n * KP + k) * 2) = h;
        *(__nv_bfloat16*)(smem + WL_OFF + (n * KP + k) * 2) = l;
    }
    if (tid < HID) { b1s[tid] = b1[tid]; w2s[tid] = W2[tid]; }
    const float b2v = b2[0];

    // ---- ldmatrix per-lane base addresses
    // A (x4 = one m16k16 tile): lanes 0-15 -> rows m0+l, col k0;
    //                           lanes 16-31 -> rows m0+(l-16), col k0+8.
    const uint32_t a_off = (((uint32_t)(lane & 15)) * KP +
                            ((uint32_t)(lane >> 4)) * 8) * 2;
    const uint32_t axh = sb + XH_OFF + (uint32_t)(wid * 32) * KP * 2 + a_off;
    const uint32_t axl = sb + XL_OFF + (uint32_t)(wid * 32) * KP * 2 + a_off;
    // B (x4 = two k16n8 tiles, n0..n0+15): n = (l&7) + (l>=16)*8; kadd = ((l>>3)&1)*8
    const uint32_t b_off = (((uint32_t)((lane & 7) + ((lane >> 4) << 3))) * KP +
                            ((uint32_t)((lane >> 3) & 1)) * 8) * 2;
    const uint32_t bwh = sb + WH_OFF + b_off;
    const uint32_t bwl = sb + WL_OFF + b_off;
    const uint32_t MT_STRIDE = 16 * KP * 2;   // 4352 B per 16-row tile group

    // pooling identity: thread = (dp dim-pair 0..63, ph node-half 0..1)
    const int dp = tid & 63;
    const int ph = tid >> 6;

    float m_run = -CUDART_INF_F;
    float s_run = 0.f;
    float pacc0 = 0.f, pacc1 = 0.f;   // dims 2dp, 2dp+1 over node-half ph

    __syncthreads();

    for (int cs = start; cs < end; cs += CHUNK) {
        const int c = min(CHUNK, end - cs);
        __syncthreads();   // xh/xl/es from previous chunk fully consumed

        // ---- load x chunk -> bf16 hi/lo [node][k]. thread = (kp=dp, nh=ph):
        // float2 LDG coalesced; STS.32 lanes consecutive -> conflict-free.
        {
            const int n0 = ph * 64;
            if (c == CHUNK) {
                #pragma unroll 4
                for (int i = 0; i < 64; ++i) {
                    const int n = n0 + i;
                    const float2 v = *((const float2*)(x + (size_t)(cs + n) * IN_DIM) + dp);
                    uint32_t lo, hi = pack_bf16x2(v.x, v.y, lo);
                    *(uint32_t*)(smem + XH_OFF + n * (KP * 2) + dp * 4) = hi;
                    *(uint32_t*)(smem + XL_OFF + n * (KP * 2) + dp * 4) = lo;
                }
            } else {
                #pragma unroll 4
                for (int i = 0; i < 64; ++i) {
                    const int n = n0 + i;
                    float2 v = make_float2(0.f, 0.f);
                    if (n < c)
                        v = *((const float2*)(x + (size_t)(cs + n) * IN_DIM) + dp);
                    uint32_t lo, hi = pack_bf16x2(v.x, v.y, lo);
                    *(uint32_t*)(smem + XH_OFF + n * (KP * 2) + dp * 4) = hi;
                    *(uint32_t*)(smem + XL_OFF + n * (KP * 2) + dp * 4) = lo;
                }
            }
        }
        __syncthreads();

        // ---- MLP: warp computes D[32 x 64] = x[32 x 128] @ W1[128 x 64]
        {
            float acc[2][8][4];
            #pragma unroll
            for (int mt = 0; mt < 2; ++mt)
                #pragma unroll
                for (int nt = 0; nt < 8; ++nt)
                    #pragma unroll
                    for (int q = 0; q < 4; ++q) acc[mt][nt][q] = 0.f;

            #pragma unroll 1
            for (int ks = 0; ks < 8; ++ks) {
                const uint32_t kb = (uint32_t)ks * 32;   // 16 bf16 = 32 B
                uint32_t ah[2][4], bb[4][4];

                // pass 0: Ah x Bh
                ldmx4(axh + kb, ah[0]);
                ldmx4(axh + MT_STRIDE + kb, ah[1]);
                #pragma unroll
                for (int np = 0; np < 4; ++np)
                    ldmx4(bwh + (uint32_t)np * MT_STRIDE + kb, bb[np]);
                #pragma unroll
                for (int mt = 0; mt < 2; ++mt)
                    #pragma unroll
                    for (int np = 0; np < 4; ++np) {
                        mma16816(acc[mt][2 * np],     ah[mt], bb[np]);
                        mma16816(acc[mt][2 * np + 1], ah[mt], bb[np] + 2);
                    }

                // pass 1: Ah x Bl
                #pragma unroll
                for (int np = 0; np < 4; ++np)
                    ldmx4(bwl + (uint32_t)np * MT_STRIDE + kb, bb[np]);
                #pragma unroll
                for (int mt = 0; mt < 2; ++mt)
                    #pragma unroll
                    for (int np = 0; np < 4; ++np) {
                        mma16816(acc[mt][2 * np],     ah[mt], bb[np]);
                        mma16816(acc[mt][2 * np + 1], ah[mt], bb[np] + 2);
                    }

                // pass 2: Al x Bh
                ldmx4(axl + kb, ah[0]);
                ldmx4(axl + MT_STRIDE + kb, ah[1]);
                #pragma unroll
                for (int np = 0; np < 4; ++np)
                    ldmx4(bwh + (uint32_t)np * MT_STRIDE + kb, bb[np]);
                #pragma unroll
                for (int mt = 0; mt < 2; ++mt)
                    #pragma unroll
                    for (int np = 0; np < 4; ++np) {
                        mma16816(acc[mt][2 * np],     ah[mt], bb[np]);
                        mma16816(acc[mt][2 * np + 1], ah[mt], bb[np] + 2);
                    }
            }

            // ---- epilogue: relu + W2, reduce over lane quad -> gate per node
            float gp[2][2] = {{0.f, 0.f}, {0.f, 0.f}};   // [mtile][row/row+8]
            #pragma unroll
            for (int nt = 0; nt < 8; ++nt) {
                const int j0 = nt * 8 + (lane & 3) * 2;
                const float bj0 = b1s[j0],     bj1 = b1s[j0 + 1];
                const float wj0 = w2s[j0],     wj1 = w2s[j0 + 1];
                #pragma unroll
                for (int mt = 0; mt < 2; ++mt) {
                    gp[mt][0] = fmaf(fmaxf(acc[mt][nt][0] + bj0, 0.f), wj0, gp[mt][0]);
                    gp[mt][0] = fmaf(fmaxf(acc[mt][nt][1] + bj1, 0.f), wj1, gp[mt][0]);
                    gp[mt][1] = fmaf(fmaxf(acc[mt][nt][2] + bj0, 0.f), wj0, gp[mt][1]);
                    gp[mt][1] = fmaf(fmaxf(acc[mt][nt][3] + bj1, 0.f), wj1, gp[mt][1]);
                }
            }
            #pragma unroll
            for (int off = 1; off < 4; off <<= 1)
                #pragma unroll
                for (int mt = 0; mt < 2; ++mt) {
                    gp[mt][0] += __shfl_xor_sync(0xffffffffu, gp[mt][0], off);
                    gp[mt][1] += __shfl_xor_sync(0xffffffffu, gp[mt][1], off);
                }
            if ((lane & 3) == 0) {
                #pragma unroll
                for (int mt = 0; mt < 2; ++mt) {
                    const int node = wid * 32 + mt * 16 + (lane >> 2);
                    es[node]     = gp[mt][0] + b2v;
                    es[node + 8] = gp[mt][1] + b2v;
                }
            }
        }
        __syncthreads();

        // ---- online softmax (thread tid owns node tid; pad nodes masked)
        const float gate = (tid < c) ? es[tid] : -CUDART_INF_F;
        float v = gate;
        #pragma unroll
        for (int o = 16; o; o >>= 1) v = fmaxf(v, __shfl_xor_sync(0xffffffffu, v, o));
        if (lane == 0) red[wid] = v;
        __syncthreads();
        const float cmax  = fmaxf(fmaxf(red[0], red[1]), fmaxf(red[2], red[3]));
        const float m_new = fmaxf(m_run, cmax);
        const float resc  = expf(m_run - m_new);   // first chunk: exp(-inf) = 0

        const float e = expf(gate - m_new);        // masked nodes -> 0
        __syncthreads();   // gates + red fully read before overwrite
        es[tid] = e;
        float sv = e;
        #pragma unroll
        for (int o = 16; o; o >>= 1) sv += __shfl_xor_sync(0xffffffffu, sv, o);
        if (lane == 0) red[wid] = sv;
        __syncthreads();
        const float csum = red[0] + red[1] + red[2] + red[3];

        s_run = s_run * resc + csum;
        m_run = m_new;

        // ---- pooling: thread (dp, ph) sums e[n]*(xh+xl) for dims 2dp,2dp+1
        pacc0 *= resc;
        pacc1 *= resc;
        {
            const int n0 = ph * 64;
            #pragma unroll 4
            for (int i = 0; i < 64; ++i) {
                const int n = n0 + i;
                const float ev = es[n];                 // warp-broadcast
                const uint32_t h2 = *(const uint32_t*)(smem + XH_OFF + n * (KP * 2) + dp * 4);
                const uint32_t l2 = *(const uint32_t*)(smem + XL_OFF + n * (KP * 2) + dp * 4);
                const float v0 = __bfloat162float(__ushort_as_bfloat16((unsigned short)(h2 & 0xffff))) +
                                 __bfloat162float(__ushort_as_bfloat16((unsigned short)(l2 & 0xffff)));
                const float v1 = __bfloat162float(__ushort_as_bfloat16((unsigned short)(h2 >> 16))) +
                                 __bfloat162float(__ushort_as_bfloat16((unsigned short)(l2 >> 16)));
                pacc0 = fmaf(ev, v0, pacc0);
                pacc1 = fmaf(ev, v1, pacc1);
            }
        }
    }

    // ---- combine node-half partials, write out
    __syncthreads();
    if (ph == 1) { acc2[2 * dp] = pacc0; acc2[2 * dp + 1] = pacc1; }
    __syncthreads();
    if (ph == 0) {
        float2 o2;
        if (end > start) {
            o2.x = (pacc0 + acc2[2 * dp]) / s_run;
            o2.y = (pacc1 + acc2[2 * dp + 1]) / s_run;
        } else {
            o2.x = 0.f; o2.y = 0.f;
        }
        *((float2*)(out + (size_t)g * IN_DIM) + dp) = o2;
    }
}

// ---------------------------------------------------------------------------
extern "C" void kernel_launch(void* const* d_in, const int* in_sizes, int n_in,
                              void* d_out, int out_size)
{
    const float* x   = (const float*)d_in[0];
    const int*   b32 = (const int*)d_in[1];   // int32 view: safe for i32/i64
    const float* W1  = (const float*)d_in[2];
    const float* b1  = (const float*)d_in[3];
    const float* W2  = (const float*)d_in[4];
    const float* b2  = (const float*)d_in[5];
    float*       out = (float*)d_out;

    const int N = in_sizes[0] / IN_DIM;
    int G = out_size / IN_DIM;
    if (G > G_MAX) G = G_MAX;

    seg_offsets_kernel<<<(N + 1 + 255) / 256, 256>>>(b32, N, G);

    cudaFuncSetAttribute(attn_pool_kernel,
                         cudaFuncAttributeMaxDynamicSharedMemorySize, SMEM_TOTAL);
    attn_pool_kernel<<<G, THREADS, SMEM_TOTAL>>>(x, W1, b1, W2, b2, out);
}

// round 10
// speedup vs baseline: 2.1086x; 1.4435x over previous
#include <cuda_runtime.h>
#include <cuda_bf16.h>
#include <cstdint>
#include <math_constants.h>

#define IN_DIM   128
#define HID      64
#define G_MAX    8192
#define CHUNK    128
#define THREADS  256
#define KP       136        // bf16 row stride: 272 B = 17*16B -> ldmatrix conflict-free

// ---- SMEM layout (bytes); all tile bases 16B-aligned
#define XH_OFF    0                         // x hi  [128 nodes][KP] bf16 = 34816
#define XL_OFF    34816                     // x lo
#define WH_OFF    69632                     // W1^T hi [64 n][KP] bf16 = 17408
#define WL_OFF    87040                     // W1^T lo
#define B1S_OFF   104448                    // 64 f32
#define W2S_OFF   104704                    // 64 f32
#define ES_OFF    104960                    // 128 f32 (gates, then exp weights)
#define ACC2_OFF  105472                    // 3*128 f32 (pool quarter-combine)
#define RED_OFF   107008                    // 8 f32
#define SMEM_TOTAL 107072                   // x2 CTA = 214 KB <= 228 KB/SM

__device__ int g_seg_start[G_MAX + 1];

// ---------------------------------------------------------------------------
// Kernel 1: segment offsets from sorted batch (int32 view; inline i64 detect).
// ---------------------------------------------------------------------------
__global__ void seg_offsets_kernel(const int* __restrict__ b32, int n, int G)
{
    int i = blockIdx.x * blockDim.x + threadIdx.x;
    if (i > n) return;
    const int s = (b32[(n / 2) | 1] == 0) ? 2 : 1;   // int64 -> stride 2 (low word)
    int cur  = (i < n) ? b32[(size_t)i * s]       : G;
    int prev = (i > 0) ? b32[(size_t)(i - 1) * s] : -1;
    cur  = min(max(cur,  -1), G);
    prev = min(max(prev, -1), G);
    for (int g = prev + 1; g <= cur; ++g)
        g_seg_start[g] = i;
}

// ---------------------------------------------------------------------------
// baseline-feature tensor ops (sm_80+, legal at compute_103)
// ---------------------------------------------------------------------------
__device__ __forceinline__ uint32_t smem_u32(const void* p)
{
    uint32_t a;
    asm("{ .reg .u64 t; cvta.to.shared.u64 t, %1; cvt.u32.u64 %0, t; }"
        : "=r"(a) : "l"(p));
    return a;
}

__device__ __forceinline__ void ldmx4(uint32_t addr, uint32_t* r)
{
    asm volatile("ldmatrix.sync.aligned.m8n8.x4.shared.b16 {%0,%1,%2,%3}, [%4];"
                 : "=r"(r[0]), "=r"(r[1]), "=r"(r[2]), "=r"(r[3]) : "r"(addr));
}

__device__ __forceinline__ void mma16816(float* c, const uint32_t* a,
                                         const uint32_t* b)
{
    asm volatile("mma.sync.aligned.m16n8k16.row.col.f32.bf16.bf16.f32 "
                 "{%0,%1,%2,%3}, {%4,%5,%6,%7}, {%8,%9}, {%0,%1,%2,%3};"
                 : "+f"(c[0]), "+f"(c[1]), "+f"(c[2]), "+f"(c[3])
                 : "r"(a[0]), "r"(a[1]), "r"(a[2]), "r"(a[3]),
                   "r"(b[0]), "r"(b[1]));
}

__device__ __forceinline__ uint32_t pack_bf16x2(float v0, float v1,
                                                uint32_t& lo_out)
{
    const __nv_bfloat16 h0 = __float2bfloat16(v0);
    const __nv_bfloat16 h1 = __float2bfloat16(v1);
    const __nv_bfloat16 l0 = __float2bfloat16(v0 - __bfloat162float(h0));
    const __nv_bfloat16 l1 = __float2bfloat16(v1 - __bfloat162float(h1));
    lo_out = ((uint32_t)__bfloat16_as_ushort(l1) << 16) |
              (uint32_t)__bfloat16_as_ushort(l0);
    return ((uint32_t)__bfloat16_as_ushort(h1) << 16) |
            (uint32_t)__bfloat16_as_ushort(h0);
}

// ---------------------------------------------------------------------------
// Kernel 2: fused gate-MLP (mma.sync bf16 hi/lo split) + softmax + pooling.
// One CTA per graph, 256 threads (8 warps). Per chunk:
//   stage x -> bf16 hi/lo [node][k];  D = Ah*Bh + Ah*Bl + Al*Bh (fp32 accum);
//   warp w owns nodes 16w..16w+15 (1 m16 tile) x all 64 hid (8 n8 tiles);
//   epilogue relu+W2 -> gate/node; online softmax; pool from xh+xl.
// ---------------------------------------------------------------------------
__global__ __launch_bounds__(THREADS, 2)
void attn_pool_kernel(const float* __restrict__ x,
                      const float* __restrict__ W1,
                      const float* __restrict__ b1,
                      const float* __restrict__ W2,
                      const float* __restrict__ b2,
                      float* __restrict__ out)
{
    extern __shared__ char smem[];
    float* b1s  = (float*)(smem + B1S_OFF);
    float* w2s  = (float*)(smem + W2S_OFF);
    float* es   = (float*)(smem + ES_OFF);
    float* acc2 = (float*)(smem + ACC2_OFF);
    float* red  = (float*)(smem + RED_OFF);

    const uint32_t sb = smem_u32(smem);

    const int tid  = threadIdx.x;
    const int lane = tid & 31;
    const int wid  = tid >> 5;        // 0..7
    const int g    = blockIdx.x;

    const int start = g_seg_start[g];
    const int end   = g_seg_start[g + 1];

    // ---- stage W1^T hi/lo [n][k] (one-time; matches col-major B fragment)
    for (int e = tid; e < HID * IN_DIM; e += THREADS) {
        const int n = e & (HID - 1);
        const int k = e >> 6;
        const float v = W1[k * HID + n];
        const __nv_bfloat16 h = __float2bfloat16(v);
        const __nv_bfloat16 l = __float2bfloat16(v - __bfloat162float(h));
        *(__nv_bfloat16*)(smem + WH_OFF + (n * KP + k) * 2) = h;
        *(__nv_bfloat16*)(smem + WL_OFF + (n * KP + k) * 2) = l;
    }
    if (tid < HID) { b1s[tid] = b1[tid]; w2s[tid] = W2[tid]; }
    const float b2v = b2[0];

    // ---- ldmatrix per-lane base addresses
    // A (x4 = one m16k16 tile): lanes 0-15 -> rows m0+l; lanes 16-31 -> +8 cols
    const uint32_t a_off = (((uint32_t)(lane & 15)) * KP +
                            ((uint32_t)(lane >> 4)) * 8) * 2;
    const uint32_t axh = sb + XH_OFF + (uint32_t)(wid * 16) * KP * 2 + a_off;
    const uint32_t axl = sb + XL_OFF + (uint32_t)(wid * 16) * KP * 2 + a_off;
    // B (x4 = two k16n8 tiles): n = (l&7) + (l>=16)*8; kadd = ((l>>3)&1)*8
    const uint32_t b_off = (((uint32_t)((lane & 7) + ((lane >> 4) << 3))) * KP +
                            ((uint32_t)((lane >> 3) & 1)) * 8) * 2;
    const uint32_t bwh = sb + WH_OFF + b_off;
    const uint32_t bwl = sb + WL_OFF + b_off;
    const uint32_t MT_STRIDE = 16 * KP * 2;   // 4352 B per 16-row tile group

    // load/pool identity: thread = (dp dim-pair 0..63, ph node-quarter 0..3)
    const int dp = tid & 63;
    const int ph = tid >> 6;

    float m_run = -CUDART_INF_F;
    float s_run = 0.f;
    float pacc0 = 0.f, pacc1 = 0.f;   // dims 2dp, 2dp+1 over node-quarter ph

    __syncthreads();

    for (int cs = start; cs < end; cs += CHUNK) {
        const int c = min(CHUNK, end - cs);
        __syncthreads();   // xh/xl/es from previous chunk fully consumed

        // ---- load x chunk -> bf16 hi/lo [node][k]. thread = (kp=dp, quarter):
        // float2 LDG coalesced; STS.32 lanes consecutive -> conflict-free.
        {
            const int n0 = ph * 32;
            if (c == CHUNK) {
                #pragma unroll 4
                for (int i = 0; i < 32; ++i) {
                    const int n = n0 + i;
                    const float2 v = *((const float2*)(x + (size_t)(cs + n) * IN_DIM) + dp);
                    uint32_t lo, hi = pack_bf16x2(v.x, v.y, lo);
                    *(uint32_t*)(smem + XH_OFF + n * (KP * 2) + dp * 4) = hi;
                    *(uint32_t*)(smem + XL_OFF + n * (KP * 2) + dp * 4) = lo;
                }
            } else {
                #pragma unroll 4
                for (int i = 0; i < 32; ++i) {
                    const int n = n0 + i;
                    float2 v = make_float2(0.f, 0.f);
                    if (n < c)
                        v = *((const float2*)(x + (size_t)(cs + n) * IN_DIM) + dp);
                    uint32_t lo, hi = pack_bf16x2(v.x, v.y, lo);
                    *(uint32_t*)(smem + XH_OFF + n * (KP * 2) + dp * 4) = hi;
                    *(uint32_t*)(smem + XL_OFF + n * (KP * 2) + dp * 4) = lo;
                }
            }
        }
        __syncthreads();

        // ---- MLP: warp computes D[16 x 64] = x[16 x 128] @ W1[128 x 64]
        {
            float acc[8][4];
            #pragma unroll
            for (int nt = 0; nt < 8; ++nt)
                #pragma unroll
                for (int q = 0; q < 4; ++q) acc[nt][q] = 0.f;

            #pragma unroll 1
            for (int ks = 0; ks < 8; ++ks) {
                const uint32_t kb = (uint32_t)ks * 32;   // 16 bf16 = 32 B
                uint32_t ah[4], al[4], bh[4][4], bl[4][4];

                ldmx4(axh + kb, ah);
                ldmx4(axl + kb, al);
                #pragma unroll
                for (int np = 0; np < 4; ++np) {
                    ldmx4(bwh + (uint32_t)np * MT_STRIDE + kb, bh[np]);
                    ldmx4(bwl + (uint32_t)np * MT_STRIDE + kb, bl[np]);
                }
                #pragma unroll
                for (int np = 0; np < 4; ++np) {
                    // Ah*Bh + Ah*Bl + Al*Bh
                    mma16816(acc[2 * np],     ah, bh[np]);
                    mma16816(acc[2 * np + 1], ah, bh[np] + 2);
                    mma16816(acc[2 * np],     ah, bl[np]);
                    mma16816(acc[2 * np + 1], ah, bl[np] + 2);
                    mma16816(acc[2 * np],     al, bh[np]);
                    mma16816(acc[2 * np + 1], al, bh[np] + 2);
                }
            }

            // ---- epilogue: relu + W2, reduce over lane quad -> gate per node
            float gp0 = 0.f, gp1 = 0.f;   // rows (lane>>2), (lane>>2)+8
            #pragma unroll
            for (int nt = 0; nt < 8; ++nt) {
                const int j0 = nt * 8 + (lane & 3) * 2;
                const float bj0 = b1s[j0], bj1 = b1s[j0 + 1];
                const float wj0 = w2s[j0], wj1 = w2s[j0 + 1];
                gp0 = fmaf(fmaxf(acc[nt][0] + bj0, 0.f), wj0, gp0);
                gp0 = fmaf(fmaxf(acc[nt][1] + bj1, 0.f), wj1, gp0);
                gp1 = fmaf(fmaxf(acc[nt][2] + bj0, 0.f), wj0, gp1);
                gp1 = fmaf(fmaxf(acc[nt][3] + bj1, 0.f), wj1, gp1);
            }
            #pragma unroll
            for (int off = 1; off < 4; off <<= 1) {
                gp0 += __shfl_xor_sync(0xffffffffu, gp0, off);
                gp1 += __shfl_xor_sync(0xffffffffu, gp1, off);
            }
            if ((lane & 3) == 0) {
                const int node = wid * 16 + (lane >> 2);
                es[node]     = gp0 + b2v;
                es[node + 8] = gp1 + b2v;
            }
        }
        __syncthreads();

        // ---- online softmax (threads 0..127 own nodes; others run masked)
        const float gate = (tid < c) ? es[tid] : -CUDART_INF_F;
        float v = gate;
        #pragma unroll
        for (int o = 16; o; o >>= 1) v = fmaxf(v, __shfl_xor_sync(0xffffffffu, v, o));
        if (lane == 0) red[wid] = v;
        __syncthreads();
        float cmax = red[0];
        #pragma unroll
        for (int w = 1; w < THREADS / 32; ++w) cmax = fmaxf(cmax, red[w]);
        const float m_new = fmaxf(m_run, cmax);
        const float resc  = expf(m_run - m_new);   // first chunk: exp(-inf) = 0

        const float e = expf(gate - m_new);        // masked nodes -> 0
        __syncthreads();   // gates + red fully read before overwrite
        if (tid < CHUNK) es[tid] = e;
        float sv = (tid < CHUNK) ? e : 0.f;
        #pragma unroll
        for (int o = 16; o; o >>= 1) sv += __shfl_xor_sync(0xffffffffu, sv, o);
        if (lane == 0) red[wid] = sv;
        __syncthreads();
        float csum = red[0];
        #pragma unroll
        for (int w = 1; w < THREADS / 32; ++w) csum += red[w];

        s_run = s_run * resc + csum;
        m_run = m_new;

        // ---- pooling: thread (dp, ph) sums e[n]*(xh+xl), dims 2dp, 2dp+1
        pacc0 *= resc;
        pacc1 *= resc;
        {
            const int n0 = ph * 32;
            #pragma unroll 4
            for (int i = 0; i < 32; ++i) {
                const int n = n0 + i;
                const float ev = es[n];                 // warp-broadcast
                const uint32_t h2 = *(const uint32_t*)(smem + XH_OFF + n * (KP * 2) + dp * 4);
                const uint32_t l2 = *(const uint32_t*)(smem + XL_OFF + n * (KP * 2) + dp * 4);
                const float v0 = __bfloat162float(__ushort_as_bfloat16((unsigned short)(h2 & 0xffff))) +
                                 __bfloat162float(__ushort_as_bfloat16((unsigned short)(l2 & 0xffff)));
                const float v1 = __bfloat162float(__ushort_as_bfloat16((unsigned short)(h2 >> 16))) +
                                 __bfloat162float(__ushort_as_bfloat16((unsigned short)(l2 >> 16)));
                pacc0 = fmaf(ev, v0, pacc0);
                pacc1 = fmaf(ev, v1, pacc1);
            }
        }
    }

    // ---- combine node-quarter partials, write out
    __syncthreads();
    if (ph > 0) {
        acc2[(ph - 1) * IN_DIM + 2 * dp]     = pacc0;
        acc2[(ph - 1) * IN_DIM + 2 * dp + 1] = pacc1;
    }
    __syncthreads();
    if (ph == 0) {
        float2 o2 = make_float2(0.f, 0.f);
        if (end > start) {
            float s0 = pacc0, s1 = pacc1;
            #pragma unroll
            for (int q = 0; q < 3; ++q) {
                s0 += acc2[q * IN_DIM + 2 * dp];
                s1 += acc2[q * IN_DIM + 2 * dp + 1];
            }
            o2.x = s0 / s_run;
            o2.y = s1 / s_run;
        }
        *((float2*)(out + (size_t)g * IN_DIM) + dp) = o2;
    }
}

// ---------------------------------------------------------------------------
extern "C" void kernel_launch(void* const* d_in, const int* in_sizes, int n_in,
                              void* d_out, int out_size)
{
    const float* x   = (const float*)d_in[0];
    const int*   b32 = (const int*)d_in[1];   // int32 view: safe for i32/i64
    const float* W1  = (const float*)d_in[2];
    const float* b1  = (const float*)d_in[3];
    const float* W2  = (const float*)d_in[4];
    const float* b2  = (const float*)d_in[5];
    float*       out = (float*)d_out;

    const int N = in_sizes[0] / IN_DIM;
    int G = out_size / IN_DIM;
    if (G > G_MAX) G = G_MAX;

    seg_offsets_kernel<<<(N + 1 + 255) / 256, 256>>>(b32, N, G);

    cudaFuncSetAttribute(attn_pool_kernel,
                         cudaFuncAttributeMaxDynamicSharedMemorySize, SMEM_TOTAL);
    attn_pool_kernel<<<G, THREADS, SMEM_TOTAL>>>(x, W1, b1, W2, b2, out);
}

// round 11
// speedup vs baseline: 2.2395x; 1.0621x over previous
#include <cuda_runtime.h>
#include <cuda_bf16.h>
#include <cstdint>
#include <math_constants.h>

#define IN_DIM   128
#define HID      64
#define G_MAX    8192
#define CHUNK    64
#define THREADS  256
#define KP       136        // bf16 row stride: 272 B = 17*16B -> ldmatrix conflict-free
#define MT_STRIDE (16 * KP * 2)   // 4352 B per 16-row tile group

// ---- SMEM layout (bytes); tile bases 16B-aligned
#define WH_OFF    0                         // W1^T hi [64 n][KP] bf16 = 17408
#define WL_OFF    17408                     // W1^T lo
#define XB_OFF    34816                     // x bufs: [buf][{hi,lo}][64][KP]
#define XBUF_SZ   34816                     // one buf = hi(17408) + lo(17408)
#define B1S_OFF   104448                    // 64 f32
#define W2S_OFF   104704                    // 64 f32
#define GP_OFF    104960                    // 2*64 f32 gate partials
#define ES_OFF    105472                    // 64 f32 exp weights (+pad)
#define ACC2_OFF  105984                    // 3*128 f32 pool quarter-combine
#define RED_OFF   107520                    // 8 f32
#define SMEM_TOTAL 107552                   // x2 CTA = 215 KB <= 228 KB/SM

__device__ int g_seg_start[G_MAX + 1];

// ---------------------------------------------------------------------------
// Kernel 1: segment offsets from sorted batch (int32 view; inline i64 detect).
// ---------------------------------------------------------------------------
__global__ void seg_offsets_kernel(const int* __restrict__ b32, int n, int G)
{
    int i = blockIdx.x * blockDim.x + threadIdx.x;
    if (i > n) return;
    const int s = (b32[(n / 2) | 1] == 0) ? 2 : 1;   // int64 -> stride 2 (low word)
    int cur  = (i < n) ? b32[(size_t)i * s]       : G;
    int prev = (i > 0) ? b32[(size_t)(i - 1) * s] : -1;
    cur  = min(max(cur,  -1), G);
    prev = min(max(prev, -1), G);
    for (int g = prev + 1; g <= cur; ++g)
        g_seg_start[g] = i;
}

// ---------------------------------------------------------------------------
// baseline-feature tensor ops (sm_80+, legal at compute_103)
// ---------------------------------------------------------------------------
__device__ __forceinline__ uint32_t smem_u32(const void* p)
{
    uint32_t a;
    asm("{ .reg .u64 t; cvta.to.shared.u64 t, %1; cvt.u32.u64 %0, t; }"
        : "=r"(a) : "l"(p));
    return a;
}

__device__ __forceinline__ void ldmx4(uint32_t addr, uint32_t* r)
{
    asm volatile("ldmatrix.sync.aligned.m8n8.x4.shared.b16 {%0,%1,%2,%3}, [%4];"
                 : "=r"(r[0]), "=r"(r[1]), "=r"(r[2]), "=r"(r[3]) : "r"(addr));
}

__device__ __forceinline__ void mma16816(float* c, const uint32_t* a,
                                         const uint32_t* b)
{
    asm volatile("mma.sync.aligned.m16n8k16.row.col.f32.bf16.bf16.f32 "
                 "{%0,%1,%2,%3}, {%4,%5,%6,%7}, {%8,%9}, {%0,%1,%2,%3};"
                 : "+f"(c[0]), "+f"(c[1]), "+f"(c[2]), "+f"(c[3])
                 : "r"(a[0]), "r"(a[1]), "r"(a[2]), "r"(a[3]),
                   "r"(b[0]), "r"(b[1]));
}

__device__ __forceinline__ uint32_t pack_bf16x2(float v0, float v1,
                                                uint32_t& lo_out)
{
    const __nv_bfloat16 h0 = __float2bfloat16(v0);
    const __nv_bfloat16 h1 = __float2bfloat16(v1);
    const __nv_bfloat16 l0 = __float2bfloat16(v0 - __bfloat162float(h0));
    const __nv_bfloat16 l1 = __float2bfloat16(v1 - __bfloat162float(h1));
    lo_out = ((uint32_t)__bfloat16_as_ushort(l1) << 16) |
              (uint32_t)__bfloat16_as_ushort(l0);
    return ((uint32_t)__bfloat16_as_ushort(h1) << 16) |
            (uint32_t)__bfloat16_as_ushort(h0);
}

// ---------------------------------------------------------------------------
// Kernel 2: fused gate-MLP (mma.sync bf16 hi/lo split) + softmax + pooling,
// software-pipelined at chunk level (double-buffered staging, prefetch in
// registers). One CTA per graph, 256 threads (8 warps).
// Warp (mg 0..3, nh 0..1): nodes 16mg..16mg+15 (m16 tile) x hid 32nh..+31.
// ---------------------------------------------------------------------------
__global__ __launch_bounds__(THREADS, 2)
void attn_pool_kernel(const float* __restrict__ x,
                      const float* __restrict__ W1,
                      const float* __restrict__ b1,
                      const float* __restrict__ W2,
                      const float* __restrict__ b2,
                      float* __restrict__ out)
{
    extern __shared__ char smem[];
    float* b1s  = (float*)(smem + B1S_OFF);
    float* w2s  = (float*)(smem + W2S_OFF);
    float* gps  = (float*)(smem + GP_OFF);
    float* es   = (float*)(smem + ES_OFF);
    float* acc2 = (float*)(smem + ACC2_OFF);
    float* red  = (float*)(smem + RED_OFF);

    const uint32_t sb = smem_u32(smem);

    const int tid  = threadIdx.x;
    const int lane = tid & 31;
    const int wid  = tid >> 5;        // 0..7
    const int mg   = wid & 3;         // m-group: nodes 16mg..16mg+15
    const int nh   = wid >> 2;        // hid half: 32nh..32nh+31
    const int g    = blockIdx.x;

    const int start = g_seg_start[g];
    const int end   = g_seg_start[g + 1];

    // ---- stage W1^T hi/lo [n][k] (one-time; matches col-major B fragment)
    for (int e = tid; e < HID * IN_DIM; e += THREADS) {
        const int n = e & (HID - 1);
        const int k = e >> 6;
        const float v = W1[k * HID + n];
        const __nv_bfloat16 h = __float2bfloat16(v);
        const __nv_bfloat16 l = __float2bfloat16(v - __bfloat162float(h));
        *(__nv_bfloat16*)(smem + WH_OFF + (n * KP + k) * 2) = h;
        *(__nv_bfloat16*)(smem + WL_OFF + (n * KP + k) * 2) = l;
    }
    if (tid < HID) { b1s[tid] = b1[tid]; w2s[tid] = W2[tid]; }
    const float b2v = b2[0];

    // ---- ldmatrix per-lane offsets (same fragment math as validated R9/R10)
    const uint32_t a_off = (((uint32_t)(lane & 15)) * KP +
                            ((uint32_t)(lane >> 4)) * 8) * 2 +
                           (uint32_t)(mg * 16) * KP * 2;
    const uint32_t b_off = (((uint32_t)((lane & 7) + ((lane >> 4) << 3))) * KP +
                            ((uint32_t)((lane >> 3) & 1)) * 8) * 2;
    const uint32_t bwh = sb + WH_OFF + (uint32_t)(nh * 32) * KP * 2 + b_off;
    const uint32_t bwl = sb + WL_OFF + (uint32_t)(nh * 32) * KP * 2 + b_off;

    // load/pool identity: thread = (dp dim-pair 0..63, ph node-quarter 0..3)
    const int dp = tid & 63;
    const int ph = tid >> 6;

    float m_run = -CUDART_INF_F;
    float s_run = 0.f;
    float pacc0 = 0.f, pacc1 = 0.f;

    // ---- prologue: stage chunk 0 into buffer 0
    if (start < end) {
        const int c0 = min(CHUNK, end - start);
        #pragma unroll 4
        for (int i = 0; i < 16; ++i) {
            const int n = ph * 16 + i;
            float2 v = make_float2(0.f, 0.f);
            if (n < c0)
                v = *((const float2*)(x + (size_t)(start + n) * IN_DIM) + dp);
            uint32_t lo, hi = pack_bf16x2(v.x, v.y, lo);
            *(uint32_t*)(smem + XB_OFF + n * (KP * 2) + dp * 4) = hi;
            *(uint32_t*)(smem + XB_OFF + 17408 + n * (KP * 2) + dp * 4) = lo;
        }
    }
    __syncthreads();

    for (int cs = start, p = 0; cs < end; cs += CHUNK, p ^= 1) {
        const int c   = min(CHUNK, end - cs);
        const int cs2 = cs + CHUNK;
        const bool hn = cs2 < end;
        const int c2  = hn ? min(CHUNK, end - cs2) : 0;

        // ---- (b) prefetch next chunk into registers (latency hidden by MMA)
        float2 v[16];
        if (hn) {
            #pragma unroll
            for (int i = 0; i < 16; ++i) {
                const int n = ph * 16 + i;
                v[i] = make_float2(0.f, 0.f);
                if (n < c2)
                    v[i] = *((const float2*)(x + (size_t)(cs2 + n) * IN_DIM) + dp);
            }
        }

        // ---- (c) MMA: warp computes D[16 x 32] = x[16 x 128] @ W1[128 x 32]
        {
            const uint32_t xbase = sb + XB_OFF + (uint32_t)p * XBUF_SZ;
            const uint32_t axh = xbase + a_off;
            const uint32_t axl = xbase + 17408 + a_off;

            float acc[4][4];
            #pragma unroll
            for (int nt = 0; nt < 4; ++nt)
                #pragma unroll
                for (int q = 0; q < 4; ++q) acc[nt][q] = 0.f;

            #pragma unroll 1
            for (int ks = 0; ks < 8; ++ks) {
                const uint32_t kb = (uint32_t)ks * 32;   // 16 bf16 = 32 B
                uint32_t ah[4], al[4], bh[2][4], bl[2][4];
                ldmx4(axh + kb, ah);
                ldmx4(axl + kb, al);
                #pragma unroll
                for (int np = 0; np < 2; ++np) {
                    ldmx4(bwh + (uint32_t)np * MT_STRIDE + kb, bh[np]);
                    ldmx4(bwl + (uint32_t)np * MT_STRIDE + kb, bl[np]);
                }
                #pragma unroll
                for (int np = 0; np < 2; ++np) {
                    mma16816(acc[2 * np],     ah, bh[np]);
                    mma16816(acc[2 * np + 1], ah, bh[np] + 2);
                    mma16816(acc[2 * np],     ah, bl[np]);
                    mma16816(acc[2 * np + 1], ah, bl[np] + 2);
                    mma16816(acc[2 * np],     al, bh[np]);
                    mma16816(acc[2 * np + 1], al, bh[np] + 2);
                }
            }

            // epilogue: relu + W2 partial (this hid half), quad-reduce
            float gp0 = 0.f, gp1 = 0.f;   // rows (lane>>2), (lane>>2)+8
            #pragma unroll
            for (int nt = 0; nt < 4; ++nt) {
                const int j0 = nh * 32 + nt * 8 + (lane & 3) * 2;
                const float bj0 = b1s[j0], bj1 = b1s[j0 + 1];
                const float wj0 = w2s[j0], wj1 = w2s[j0 + 1];
                gp0 = fmaf(fmaxf(acc[nt][0] + bj0, 0.f), wj0, gp0);
                gp0 = fmaf(fmaxf(acc[nt][1] + bj1, 0.f), wj1, gp0);
                gp1 = fmaf(fmaxf(acc[nt][2] + bj0, 0.f), wj0, gp1);
                gp1 = fmaf(fmaxf(acc[nt][3] + bj1, 0.f), wj1, gp1);
            }
            #pragma unroll
            for (int off = 1; off < 4; off <<= 1) {
                gp0 += __shfl_xor_sync(0xffffffffu, gp0, off);
                gp1 += __shfl_xor_sync(0xffffffffu, gp1, off);
            }
            if ((lane & 3) == 0) {
                const int node = mg * 16 + (lane >> 2);
                gps[nh * 64 + node]     = gp0;
                gps[nh * 64 + node + 8] = gp1;
            }
        }
        __syncthreads();   // (d) gate partials ready

        // ---- (e) online softmax + pooling (chunk cs, buffer p)
        const float gate = (tid < c) ? (gps[tid] + gps[64 + tid] + b2v)
                                     : -CUDART_INF_F;
        float mv = gate;
        #pragma unroll
        for (int o = 16; o; o >>= 1) mv = fmaxf(mv, __shfl_xor_sync(0xffffffffu, mv, o));
        if (lane == 0) red[wid] = mv;
        __syncthreads();
        float cmax = red[0];
        #pragma unroll
        for (int w = 1; w < THREADS / 32; ++w) cmax = fmaxf(cmax, red[w]);
        const float m_new = fmaxf(m_run, cmax);
        const float resc  = expf(m_run - m_new);   // first chunk: exp(-inf) = 0

        const float e = expf(gate - m_new);        // masked nodes -> 0
        __syncthreads();   // red fully read before overwrite
        if (tid < CHUNK) es[tid] = e;
        float sv = (tid < CHUNK) ? e : 0.f;
        #pragma unroll
        for (int o = 16; o; o >>= 1) sv += __shfl_xor_sync(0xffffffffu, sv, o);
        if (lane == 0) red[wid] = sv;
        __syncthreads();
        float csum = red[0];
        #pragma unroll
        for (int w = 1; w < THREADS / 32; ++w) csum += red[w];

        s_run = s_run * resc + csum;
        m_run = m_new;

        pacc0 *= resc;
        pacc1 *= resc;
        {
            const char* xb = smem + XB_OFF + p * XBUF_SZ;
            #pragma unroll 4
            for (int i = 0; i < 16; ++i) {
                const int n = ph * 16 + i;
                const float ev = es[n];                 // warp-broadcast
                const uint32_t h2 = *(const uint32_t*)(xb + n * (KP * 2) + dp * 4);
                const uint32_t l2 = *(const uint32_t*)(xb + 17408 + n * (KP * 2) + dp * 4);
                const float v0 = __bfloat162float(__ushort_as_bfloat16((unsigned short)(h2 & 0xffff))) +
                                 __bfloat162float(__ushort_as_bfloat16((unsigned short)(l2 & 0xffff)));
                const float v1 = __bfloat162float(__ushort_as_bfloat16((unsigned short)(h2 >> 16))) +
                                 __bfloat162float(__ushort_as_bfloat16((unsigned short)(l2 >> 16)));
                pacc0 = fmaf(ev, v0, pacc0);
                pacc1 = fmaf(ev, v1, pacc1);
            }
        }

        // ---- (f) store prefetched chunk into the other buffer
        if (hn) {
            char* xb = smem + XB_OFF + (p ^ 1) * XBUF_SZ;
            #pragma unroll
            for (int i = 0; i < 16; ++i) {
                const int n = ph * 16 + i;
                uint32_t lo, hi = pack_bf16x2(v[i].x, v[i].y, lo);
                *(uint32_t*)(xb + n * (KP * 2) + dp * 4) = hi;
                *(uint32_t*)(xb + 17408 + n * (KP * 2) + dp * 4) = lo;
            }
        }
        __syncthreads();   // (a) next buffer ready; gps/es/red reusable
    }

    // ---- combine node-quarter partials, write out
    __syncthreads();
    if (ph > 0) {
        acc2[(ph - 1) * IN_DIM + 2 * dp]     = pacc0;
        acc2[(ph - 1) * IN_DIM + 2 * dp + 1] = pacc1;
    }
    __syncthreads();
    if (ph == 0) {
        float2 o2 = make_float2(0.f, 0.f);
        if (end > start) {
            float s0 = pacc0, s1 = pacc1;
            #pragma unroll
            for (int q = 0; q < 3; ++q) {
                s0 += acc2[q * IN_DIM + 2 * dp];
                s1 += acc2[q * IN_DIM + 2 * dp + 1];
            }
            o2.x = s0 / s_run;
            o2.y = s1 / s_run;
        }
        *((float2*)(out + (size_t)g * IN_DIM) + dp) = o2;
    }
}

// ---------------------------------------------------------------------------
extern "C" void kernel_launch(void* const* d_in, const int* in_sizes, int n_in,
                              void* d_out, int out_size)
{
    const float* x   = (const float*)d_in[0];
    const int*   b32 = (const int*)d_in[1];   // int32 view: safe for i32/i64
    const float* W1  = (const float*)d_in[2];
    const float* b1  = (const float*)d_in[3];
    const float* W2  = (const float*)d_in[4];
    const float* b2  = (const float*)d_in[5];
    float*       out = (float*)d_out;

    const int N = in_sizes[0] / IN_DIM;
    int G = out_size / IN_DIM;
    if (G > G_MAX) G = G_MAX;

    seg_offsets_kernel<<<(N + 1 + 255) / 256, 256>>>(b32, N, G);

    cudaFuncSetAttribute(attn_pool_kernel,
                         cudaFuncAttributeMaxDynamicSharedMemorySize, SMEM_TOTAL);
    attn_pool_kernel<<<G, THREADS, SMEM_TOTAL>>>(x, W1, b1, W2, b2, out);
}

// round 12
// speedup vs baseline: 2.9127x; 1.3006x over previous
#include <cuda_runtime.h>
#include <cuda_fp16.h>
#include <cstdint>
#include <math_constants.h>

#define IN_DIM   128
#define HID      64
#define G_MAX    8192
#define CHUNK    64
#define THREADS  256
#define KP       136        // fp16 row stride: 272 B = 17*16B -> ldmatrix conflict-free
#define MT_STRIDE (16 * KP * 2)   // 4352 B per 16-row tile group

// ---- SMEM layout (bytes); tile bases 16B-aligned
#define WH_OFF    0                         // W1^T fp16 [64 n][KP] = 17408
#define XB_OFF    17408                     // x bufs: [buf][{hi,lo}][64][KP]
#define XBUF_SZ   34816                     // one buf = hi(17408) + lo(17408)
#define B1S_OFF   87040                     // 64 f32
#define W2S_OFF   87296                     // 64 f32
#define GP_OFF    87552                     // 2*64 f32 gate partials
#define ES_OFF    88064                     // 64 f32 exp weights
#define ACC2_OFF  88320                     // 3*128 f32 pool quarter-combine
#define RED_OFF   89856                     // 4 f32 (+pad)
#define SMEM_TOTAL 89888                    // x2 CTA = 180 KB <= 228 KB/SM

__device__ int g_seg_start[G_MAX + 1];

// ---------------------------------------------------------------------------
// Kernel 1: segment offsets from sorted batch (int32 view; inline i64 detect).
// ---------------------------------------------------------------------------
__global__ void seg_offsets_kernel(const int* __restrict__ b32, int n, int G)
{
    int i = blockIdx.x * blockDim.x + threadIdx.x;
    if (i > n) return;
    const int s = (b32[(n / 2) | 1] == 0) ? 2 : 1;   // int64 -> stride 2 (low word)
    int cur  = (i < n) ? b32[(size_t)i * s]       : G;
    int prev = (i > 0) ? b32[(size_t)(i - 1) * s] : -1;
    cur  = min(max(cur,  -1), G);
    prev = min(max(prev, -1), G);
    for (int g = prev + 1; g <= cur; ++g)
        g_seg_start[g] = i;
}

// ---------------------------------------------------------------------------
// baseline-feature tensor ops (sm_80+, legal at compute_103)
// ---------------------------------------------------------------------------
__device__ __forceinline__ uint32_t smem_u32(const void* p)
{
    uint32_t a;
    asm("{ .reg .u64 t; cvta.to.shared.u64 t, %1; cvt.u32.u64 %0, t; }"
        : "=r"(a) : "l"(p));
    return a;
}

__device__ __forceinline__ void ldmx4(uint32_t addr, uint32_t* r)
{
    asm volatile("ldmatrix.sync.aligned.m8n8.x4.shared.b16 {%0,%1,%2,%3}, [%4];"
                 : "=r"(r[0]), "=r"(r[1]), "=r"(r[2]), "=r"(r[3]) : "r"(addr));
}

__device__ __forceinline__ void mma16816(float* c, const uint32_t* a,
                                         const uint32_t* b)
{
    asm volatile("mma.sync.aligned.m16n8k16.row.col.f32.f16.f16.f32 "
                 "{%0,%1,%2,%3}, {%4,%5,%6,%7}, {%8,%9}, {%0,%1,%2,%3};"
                 : "+f"(c[0]), "+f"(c[1]), "+f"(c[2]), "+f"(c[3])
                 : "r"(a[0]), "r"(a[1]), "r"(a[2]), "r"(a[3]),
                   "r"(b[0]), "r"(b[1]));
}

// split fp32 -> fp16 hi + fp16 lo, packed pairs
__device__ __forceinline__ uint32_t pack_h2(float v0, float v1, uint32_t& lo_out)
{
    const __half h0 = __float2half_rn(v0);
    const __half h1 = __float2half_rn(v1);
    const __half l0 = __float2half_rn(v0 - __half2float(h0));
    const __half l1 = __float2half_rn(v1 - __half2float(h1));
    lo_out = ((uint32_t)__half_as_ushort(l1) << 16) |
              (uint32_t)__half_as_ushort(l0);
    return ((uint32_t)__half_as_ushort(h1) << 16) |
            (uint32_t)__half_as_ushort(h0);
}

// ---------------------------------------------------------------------------
// Kernel 2: fused gate-MLP (mma.sync fp16, A hi/lo split, B single) +
// online softmax (2 barriers/chunk) + pooling; chunk-level software pipeline.
// One CTA per graph, 256 threads (8 warps).
// Warp (mg 0..3, nq 0..1): nodes 16mg..16mg+15 (m16 tile) x hid 32nq..+31.
// D = xh*wh + xl*wh  (fp32 accum; W fp16 error ~1e-4 abs on gate).
// ---------------------------------------------------------------------------
__global__ __launch_bounds__(THREADS, 2)
void attn_pool_kernel(const float* __restrict__ x,
                      const float* __restrict__ W1,
                      const float* __restrict__ b1,
                      const float* __restrict__ W2,
                      const float* __restrict__ b2,
                      float* __restrict__ out)
{
    extern __shared__ char smem[];
    float* b1s  = (float*)(smem + B1S_OFF);
    float* w2s  = (float*)(smem + W2S_OFF);
    float* gps  = (float*)(smem + GP_OFF);
    float* es   = (float*)(smem + ES_OFF);
    float* acc2 = (float*)(smem + ACC2_OFF);
    float* red  = (float*)(smem + RED_OFF);

    const uint32_t sb = smem_u32(smem);

    const int tid  = threadIdx.x;
    const int lane = tid & 31;
    const int wid  = tid >> 5;        // 0..7
    const int mg   = wid & 3;         // m-group: nodes 16mg..16mg+15
    const int nq   = wid >> 2;        // hid half: 32nq..32nq+31
    const int g    = blockIdx.x;

    const int start = g_seg_start[g];
    const int end   = g_seg_start[g + 1];

    // ---- stage W1^T fp16 [n][k] (one-time; col-major B fragment layout)
    for (int e = tid; e < HID * IN_DIM; e += THREADS) {
        const int n = e & (HID - 1);
        const int k = e >> 6;
        *(__half*)(smem + WH_OFF + (n * KP + k) * 2) =
            __float2half_rn(W1[k * HID + n]);
    }
    if (tid < HID) { b1s[tid] = b1[tid]; w2s[tid] = W2[tid]; }
    const float b2v = b2[0];

    // ---- ldmatrix per-lane offsets (fragment math validated R9-R11)
    const uint32_t a_off = (((uint32_t)(lane & 15)) * KP +
                            ((uint32_t)(lane >> 4)) * 8) * 2 +
                           (uint32_t)(mg * 16) * KP * 2;
    const uint32_t b_off = (((uint32_t)((lane & 7) + ((lane >> 4) << 3))) * KP +
                            ((uint32_t)((lane >> 3) & 1)) * 8) * 2;
    const uint32_t bw = sb + WH_OFF + (uint32_t)(nq * 32) * KP * 2 + b_off;

    // load/pool identity: thread = (dp dim-pair 0..63, ph node-quarter 0..3)
    const int dp = tid & 63;
    const int ph = tid >> 6;

    float m_run = -CUDART_INF_F;
    float s_run = 0.f;
    float pacc0 = 0.f, pacc1 = 0.f;

    // ---- prologue: stage chunk 0 into buffer 0 (zero-pad tail)
    if (start < end) {
        const int c0 = min(CHUNK, end - start);
        #pragma unroll 4
        for (int i = 0; i < 16; ++i) {
            const int n = ph * 16 + i;
            float2 v = make_float2(0.f, 0.f);
            if (n < c0)
                v = *((const float2*)(x + (size_t)(start + n) * IN_DIM) + dp);
            uint32_t lo, hi = pack_h2(v.x, v.y, lo);
            *(uint32_t*)(smem + XB_OFF + n * (KP * 2) + dp * 4) = hi;
            *(uint32_t*)(smem + XB_OFF + 17408 + n * (KP * 2) + dp * 4) = lo;
        }
    }
    __syncthreads();

    for (int cs = start, p = 0; cs < end; cs += CHUNK, p ^= 1) {
        const int c   = min(CHUNK, end - cs);
        const int cs2 = cs + CHUNK;
        const bool hn = cs2 < end;
        const int c2  = hn ? min(CHUNK, end - cs2) : 0;

        // ---- prefetch next chunk into registers (hidden under MMA)
        float2 v[16];
        if (hn) {
            #pragma unroll
            for (int i = 0; i < 16; ++i) {
                const int n = ph * 16 + i;
                v[i] = make_float2(0.f, 0.f);
                if (n < c2)
                    v[i] = *((const float2*)(x + (size_t)(cs2 + n) * IN_DIM) + dp);
            }
        }

        // ---- MMA: warp computes D[16 x 32] = x[16 x 128] @ W1[128 x 32]
        {
            const uint32_t xbase = sb + XB_OFF + (uint32_t)p * XBUF_SZ;
            const uint32_t axh = xbase + a_off;
            const uint32_t axl = xbase + 17408 + a_off;

            float acc[4][4];
            #pragma unroll
            for (int nt = 0; nt < 4; ++nt)
                #pragma unroll
                for (int q = 0; q < 4; ++q) acc[nt][q] = 0.f;

            #pragma unroll 1
            for (int ks = 0; ks < 8; ++ks) {
                const uint32_t kb = (uint32_t)ks * 32;   // 16 fp16 = 32 B
                uint32_t ah[4], al[4], bh[2][4];
                ldmx4(axh + kb, ah);
                ldmx4(axl + kb, al);
                #pragma unroll
                for (int np = 0; np < 2; ++np)
                    ldmx4(bw + (uint32_t)np * MT_STRIDE + kb, bh[np]);
                #pragma unroll
                for (int np = 0; np < 2; ++np) {
                    mma16816(acc[2 * np],     ah, bh[np]);
                    mma16816(acc[2 * np + 1], ah, bh[np] + 2);
                    mma16816(acc[2 * np],     al, bh[np]);
                    mma16816(acc[2 * np + 1], al, bh[np] + 2);
                }
            }

            // epilogue: relu + W2 partial (this hid half), quad-reduce
            float gp0 = 0.f, gp1 = 0.f;   // rows (lane>>2), (lane>>2)+8
            #pragma unroll
            for (int nt = 0; nt < 4; ++nt) {
                const int j0 = nq * 32 + nt * 8 + (lane & 3) * 2;
                const float bj0 = b1s[j0], bj1 = b1s[j0 + 1];
                const float wj0 = w2s[j0], wj1 = w2s[j0 + 1];
                gp0 = fmaf(fmaxf(acc[nt][0] + bj0, 0.f), wj0, gp0);
                gp0 = fmaf(fmaxf(acc[nt][1] + bj1, 0.f), wj1, gp0);
                gp1 = fmaf(fmaxf(acc[nt][2] + bj0, 0.f), wj0, gp1);
                gp1 = fmaf(fmaxf(acc[nt][3] + bj1, 0.f), wj1, gp1);
            }
            #pragma unroll
            for (int off = 1; off < 4; off <<= 1) {
                gp0 += __shfl_xor_sync(0xffffffffu, gp0, off);
                gp1 += __shfl_xor_sync(0xffffffffu, gp1, off);
            }
            if ((lane & 3) == 0) {
                const int node = mg * 16 + (lane >> 2);
                gps[nq * 64 + node]     = gp0;
                gps[nq * 64 + node + 8] = gp1;
            }
        }
        __syncthreads();   // BAR 1: gps ready; prev pooling/es reads done

        // ---- warps 0-1: per-warp softmax partials (no inner barrier)
        if (tid < CHUNK) {
            const float gate = (tid < c) ? (gps[tid] + gps[64 + tid] + b2v)
                                         : -CUDART_INF_F;
            float mw = gate;
            #pragma unroll
            for (int o = 16; o; o >>= 1)
                mw = fmaxf(mw, __shfl_xor_sync(0xffffffffu, mw, o));
            const float mws = fmaxf(mw, -1e30f);   // all-masked warp -> finite
            const float e = expf(gate - mws);      // masked: exp(-inf) = 0
            es[tid] = e;
            float sw = e;
            #pragma unroll
            for (int o = 16; o; o >>= 1)
                sw += __shfl_xor_sync(0xffffffffu, sw, o);
            if (lane == 0) { red[2 * wid] = mws; red[2 * wid + 1] = sw; }
        }

        // ---- all threads: store prefetched chunk into other buffer
        if (hn) {
            char* xb = smem + XB_OFF + (p ^ 1) * XBUF_SZ;
            #pragma unroll
            for (int i = 0; i < 16; ++i) {
                const int n = ph * 16 + i;
                uint32_t lo, hi = pack_h2(v[i].x, v[i].y, lo);
                *(uint32_t*)(xb + n * (KP * 2) + dp * 4) = hi;
                *(uint32_t*)(xb + 17408 + n * (KP * 2) + dp * 4) = lo;
            }
        }
        __syncthreads();   // BAR 2: red + es ready; next buffer staged

        // ---- combine the two warp partials analytically (all threads)
        const float m0 = red[0], s0 = red[1], m1 = red[2], s1 = red[3];
        const float m_new = fmaxf(m_run, fmaxf(m0, m1));
        const float resc  = expf(m_run - m_new);   // first chunk: 0
        const float sc0   = expf(m0 - m_new);
        const float sc1   = expf(m1 - m_new);
        s_run = s_run * resc + fmaf(s0, sc0, s1 * sc1);
        m_run = m_new;

        // ---- pooling from buffer p: thread (dp, ph), dims 2dp & 2dp+1
        pacc0 *= resc;
        pacc1 *= resc;
        {
            const float scp = (ph < 2) ? sc0 : sc1;   // node-half scale
            const char* xb = smem + XB_OFF + p * XBUF_SZ;
            #pragma unroll 4
            for (int i = 0; i < 16; ++i) {
                const int n = ph * 16 + i;
                const float ev = es[n] * scp;          // warp-broadcast LDS
                const uint32_t h2 = *(const uint32_t*)(xb + n * (KP * 2) + dp * 4);
                const uint32_t l2 = *(const uint32_t*)(xb + 17408 + n * (KP * 2) + dp * 4);
                const float v0 =
                    __half2float(__ushort_as_half((unsigned short)(h2 & 0xffff))) +
                    __half2float(__ushort_as_half((unsigned short)(l2 & 0xffff)));
                const float v1 =
                    __half2float(__ushort_as_half((unsigned short)(h2 >> 16))) +
                    __half2float(__ushort_as_half((unsigned short)(l2 >> 16)));
                pacc0 = fmaf(ev, v0, pacc0);
                pacc1 = fmaf(ev, v1, pacc1);
            }
        }
    }

    // ---- combine node-quarter partials, write out
    __syncthreads();
    if (ph > 0) {
        acc2[(ph - 1) * IN_DIM + 2 * dp]     = pacc0;
        acc2[(ph - 1) * IN_DIM + 2 * dp + 1] = pacc1;
    }
    __syncthreads();
    if (ph == 0) {
        float2 o2 = make_float2(0.f, 0.f);
        if (end > start) {
            float s0 = pacc0, s1 = pacc1;
            #pragma unroll
            for (int q = 0; q < 3; ++q) {
                s0 += acc2[q * IN_DIM + 2 * dp];
                s1 += acc2[q * IN_DIM + 2 * dp + 1];
            }
            o2.x = s0 / s_run;
            o2.y = s1 / s_run;
        }
        *((float2*)(out + (size_t)g * IN_DIM) + dp) = o2;
    }
}

// ---------------------------------------------------------------------------
extern "C" void kernel_launch(void* const* d_in, const int* in_sizes, int n_in,
                              void* d_out, int out_size)
{
    const float* x   = (const float*)d_in[0];
    const int*   b32 = (const int*)d_in[1];   // int32 view: safe for i32/i64
    const float* W1  = (const float*)d_in[2];
    const float* b1  = (const float*)d_in[3];
    const float* W2  = (const float*)d_in[4];
    const float* b2  = (const float*)d_in[5];
    float*       out = (float*)d_out;

    const int N = in_sizes[0] / IN_DIM;
    int G = out_size / IN_DIM;
    if (G > G_MAX) G = G_MAX;

    seg_offsets_kernel<<<(N + 1 + 255) / 256, 256>>>(b32, N, G);

    cudaFuncSetAttribute(attn_pool_kernel,
                         cudaFuncAttributeMaxDynamicSharedMemorySize, SMEM_TOTAL);
    attn_pool_kernel<<<G, THREADS, SMEM_TOTAL>>>(x, W1, b1, W2, b2, out);
}

// round 13
// speedup vs baseline: 4.1849x; 1.4368x over previous
#include <cuda_runtime.h>
#include <cuda_fp16.h>
#include <cstdint>
#include <math_constants.h>

#define IN_DIM   128
#define HID      64
#define G_MAX    8192
#define CHUNK    64
#define THREADS  256
#define KP       136        // fp16 row stride: 272 B = 17*16B -> ldmatrix conflict-free
#define MT_STRIDE (16 * KP * 2)   // 4352 B per 16-row tile group
#define XBUF_SZ  17408      // one x buffer: [64 nodes][KP] fp16

// ---- SMEM layout (bytes); tile bases 16B-aligned
#define WH_OFF    0                         // W1^T fp16 [64 n][KP] = 17408
#define XB_OFF    17408                     // x bufs: [buf][64][KP] fp16, x2
#define B1S_OFF   52224                     // 64 f32
#define W2S_OFF   52480                     // 64 f32
#define GP_OFF    52736                     // 2*64 f32 gate partials
#define ES_OFF    53248                     // 64 f32 exp weights
#define ACC2_OFF  53504                     // 3*128 f32 pool quarter-combine
#define RED_OFF   55040                     // 4 f32 (+pad)
#define SMEM_TOTAL 55072                    // x3 CTA = 165 KB <= 228 KB/SM

__device__ int g_seg_start[G_MAX + 1];

// ---------------------------------------------------------------------------
// Kernel 1: segment offsets from sorted batch (int32 view; inline i64 detect).
// ---------------------------------------------------------------------------
__global__ void seg_offsets_kernel(const int* __restrict__ b32, int n, int G)
{
    int i = blockIdx.x * blockDim.x + threadIdx.x;
    if (i > n) return;
    const int s = (b32[(n / 2) | 1] == 0) ? 2 : 1;   // int64 -> stride 2 (low word)
    int cur  = (i < n) ? b32[(size_t)i * s]       : G;
    int prev = (i > 0) ? b32[(size_t)(i - 1) * s] : -1;
    cur  = min(max(cur,  -1), G);
    prev = min(max(prev, -1), G);
    for (int g = prev + 1; g <= cur; ++g)
        g_seg_start[g] = i;
}

// ---------------------------------------------------------------------------
// baseline-feature tensor ops (sm_80+, legal at compute_103)
// ---------------------------------------------------------------------------
__device__ __forceinline__ uint32_t smem_u32(const void* p)
{
    uint32_t a;
    asm("{ .reg .u64 t; cvta.to.shared.u64 t, %1; cvt.u32.u64 %0, t; }"
        : "=r"(a) : "l"(p));
    return a;
}

__device__ __forceinline__ void ldmx4(uint32_t addr, uint32_t* r)
{
    asm volatile("ldmatrix.sync.aligned.m8n8.x4.shared.b16 {%0,%1,%2,%3}, [%4];"
                 : "=r"(r[0]), "=r"(r[1]), "=r"(r[2]), "=r"(r[3]) : "r"(addr));
}

__device__ __forceinline__ void mma16816(float* c, const uint32_t* a,
                                         const uint32_t* b)
{
    asm volatile("mma.sync.aligned.m16n8k16.row.col.f32.f16.f16.f32 "
                 "{%0,%1,%2,%3}, {%4,%5,%6,%7}, {%8,%9}, {%0,%1,%2,%3};"
                 : "+f"(c[0]), "+f"(c[1]), "+f"(c[2]), "+f"(c[3])
                 : "r"(a[0]), "r"(a[1]), "r"(a[2]), "r"(a[3]),
                   "r"(b[0]), "r"(b[1]));
}

__device__ __forceinline__ uint32_t pack_h2(float v0, float v1)
{
    const __half h0 = __float2half_rn(v0);
    const __half h1 = __float2half_rn(v1);
    return ((uint32_t)__half_as_ushort(h1) << 16) |
            (uint32_t)__half_as_ushort(h0);
}

// ---------------------------------------------------------------------------
// Kernel 2: fused gate-MLP (mma.sync fp16) + online softmax (2 barriers) +
// pooling; chunk-level software pipeline, single fp16 x buffer.
// One CTA per graph, 256 threads (8 warps), 3 CTAs/SM.
// Warp (mg 0..3, nq 0..1): nodes 16mg..16mg+15 (m16 tile) x hid 32nq..+31.
// ---------------------------------------------------------------------------
__global__ __launch_bounds__(THREADS, 3)
void attn_pool_kernel(const float* __restrict__ x,
                      const float* __restrict__ W1,
                      const float* __restrict__ b1,
                      const float* __restrict__ W2,
                      const float* __restrict__ b2,
                      float* __restrict__ out)
{
    extern __shared__ char smem[];
    float* b1s  = (float*)(smem + B1S_OFF);
    float* w2s  = (float*)(smem + W2S_OFF);
    float* gps  = (float*)(smem + GP_OFF);
    float* es   = (float*)(smem + ES_OFF);
    float* acc2 = (float*)(smem + ACC2_OFF);
    float* red  = (float*)(smem + RED_OFF);

    const uint32_t sb = smem_u32(smem);

    const int tid  = threadIdx.x;
    const int lane = tid & 31;
    const int wid  = tid >> 5;        // 0..7
    const int mg   = wid & 3;         // m-group: nodes 16mg..16mg+15
    const int nq   = wid >> 2;        // hid half: 32nq..32nq+31
    const int g    = blockIdx.x;

    const int start = g_seg_start[g];
    const int end   = g_seg_start[g + 1];

    // ---- stage W1^T fp16 [n][k] (one-time; col-major B fragment layout)
    for (int e = tid; e < HID * IN_DIM; e += THREADS) {
        const int n = e & (HID - 1);
        const int k = e >> 6;
        *(__half*)(smem + WH_OFF + (n * KP + k) * 2) =
            __float2half_rn(W1[k * HID + n]);
    }
    if (tid < HID) { b1s[tid] = b1[tid]; w2s[tid] = W2[tid]; }
    const float b2v = b2[0];

    // ---- ldmatrix per-lane offsets (fragment math validated R9-R12)
    const uint32_t a_off = (((uint32_t)(lane & 15)) * KP +
                            ((uint32_t)(lane >> 4)) * 8) * 2 +
                           (uint32_t)(mg * 16) * KP * 2;
    const uint32_t b_off = (((uint32_t)((lane & 7) + ((lane >> 4) << 3))) * KP +
                            ((uint32_t)((lane >> 3) & 1)) * 8) * 2;
    const uint32_t bw = sb + WH_OFF + (uint32_t)(nq * 32) * KP * 2 + b_off;

    // load/pool identity: thread = (dp dim-pair 0..63, ph node-quarter 0..3)
    const int dp = tid & 63;
    const int ph = tid >> 6;

    float m_run = -CUDART_INF_F;
    float s_run = 0.f;
    float pacc0 = 0.f, pacc1 = 0.f;

    // ---- prologue: stage chunk 0 into buffer 0 (zero-pad tail)
    if (start < end) {
        const int c0 = min(CHUNK, end - start);
        #pragma unroll 4
        for (int i = 0; i < 16; ++i) {
            const int n = ph * 16 + i;
            float2 v = make_float2(0.f, 0.f);
            if (n < c0)
                v = *((const float2*)(x + (size_t)(start + n) * IN_DIM) + dp);
            *(uint32_t*)(smem + XB_OFF + n * (KP * 2) + dp * 4) = pack_h2(v.x, v.y);
        }
    }
    __syncthreads();

    for (int cs = start, p = 0; cs < end; cs += CHUNK, p ^= 1) {
        const int c   = min(CHUNK, end - cs);
        const int cs2 = cs + CHUNK;
        const bool hn = cs2 < end;
        const int c2  = hn ? min(CHUNK, end - cs2) : 0;

        // ---- prefetch next chunk, convert to fp16 in regs (16 u32)
        uint32_t v[16];
        if (hn) {
            #pragma unroll
            for (int i = 0; i < 16; ++i) {
                const int n = ph * 16 + i;
                float2 f = make_float2(0.f, 0.f);
                if (n < c2)
                    f = *((const float2*)(x + (size_t)(cs2 + n) * IN_DIM) + dp);
                v[i] = pack_h2(f.x, f.y);
            }
        }

        // ---- MMA: warp computes D[16 x 32] = x[16 x 128] @ W1[128 x 32]
        {
            const uint32_t ax = sb + XB_OFF + (uint32_t)p * XBUF_SZ + a_off;

            float acc[4][4];
            #pragma unroll
            for (int nt = 0; nt < 4; ++nt)
                #pragma unroll
                for (int q = 0; q < 4; ++q) acc[nt][q] = 0.f;

            #pragma unroll 1
            for (int ks = 0; ks < 8; ++ks) {
                const uint32_t kb = (uint32_t)ks * 32;   // 16 fp16 = 32 B
                uint32_t ah[4], bh[2][4];
                ldmx4(ax + kb, ah);
                #pragma unroll
                for (int np = 0; np < 2; ++np)
                    ldmx4(bw + (uint32_t)np * MT_STRIDE + kb, bh[np]);
                #pragma unroll
                for (int np = 0; np < 2; ++np) {
                    mma16816(acc[2 * np],     ah, bh[np]);
                    mma16816(acc[2 * np + 1], ah, bh[np] + 2);
                }
            }

            // epilogue: relu + W2 partial (this hid half), quad-reduce
            float gp0 = 0.f, gp1 = 0.f;   // rows (lane>>2), (lane>>2)+8
            #pragma unroll
            for (int nt = 0; nt < 4; ++nt) {
                const int j0 = nq * 32 + nt * 8 + (lane & 3) * 2;
                const float bj0 = b1s[j0], bj1 = b1s[j0 + 1];
                const float wj0 = w2s[j0], wj1 = w2s[j0 + 1];
                gp0 = fmaf(fmaxf(acc[nt][0] + bj0, 0.f), wj0, gp0);
                gp0 = fmaf(fmaxf(acc[nt][1] + bj1, 0.f), wj1, gp0);
                gp1 = fmaf(fmaxf(acc[nt][2] + bj0, 0.f), wj0, gp1);
                gp1 = fmaf(fmaxf(acc[nt][3] + bj1, 0.f), wj1, gp1);
            }
            #pragma unroll
            for (int off = 1; off < 4; off <<= 1) {
                gp0 += __shfl_xor_sync(0xffffffffu, gp0, off);
                gp1 += __shfl_xor_sync(0xffffffffu, gp1, off);
            }
            if ((lane & 3) == 0) {
                const int node = mg * 16 + (lane >> 2);
                gps[nq * 64 + node]     = gp0;
                gps[nq * 64 + node + 8] = gp1;
            }
        }
        __syncthreads();   // BAR 1: gps ready; prev pooling/es reads done

        // ---- warps 0-1: per-warp softmax partials (no inner barrier)
        if (tid < CHUNK) {
            const float gate = (tid < c) ? (gps[tid] + gps[64 + tid] + b2v)
                                         : -CUDART_INF_F;
            float mw = gate;
            #pragma unroll
            for (int o = 16; o; o >>= 1)
                mw = fmaxf(mw, __shfl_xor_sync(0xffffffffu, mw, o));
            const float mws = fmaxf(mw, -1e30f);   // all-masked warp -> finite
            const float e = expf(gate - mws);      // masked: exp(-inf) = 0
            es[tid] = e;
            float sw = e;
            #pragma unroll
            for (int o = 16; o; o >>= 1)
                sw += __shfl_xor_sync(0xffffffffu, sw, o);
            if (lane == 0) { red[2 * wid] = mws; red[2 * wid + 1] = sw; }
        }

        // ---- all threads: store prefetched chunk into other buffer
        if (hn) {
            char* xb = smem + XB_OFF + (p ^ 1) * XBUF_SZ;
            #pragma unroll
            for (int i = 0; i < 16; ++i) {
                const int n = ph * 16 + i;
                *(uint32_t*)(xb + n * (KP * 2) + dp * 4) = v[i];
            }
        }
        __syncthreads();   // BAR 2: red + es ready; next buffer staged

        // ---- combine the two warp partials analytically (all threads)
        const float m0 = red[0], s0 = red[1], m1 = red[2], s1 = red[3];
        const float m_new = fmaxf(m_run, fmaxf(m0, m1));
        const float resc  = expf(m_run - m_new);   // first chunk: 0
        const float sc0   = expf(m0 - m_new);
        const float sc1   = expf(m1 - m_new);
        s_run = s_run * resc + fmaf(s0, sc0, s1 * sc1);
        m_run = m_new;

        // ---- pooling from buffer p: thread (dp, ph), dims 2dp & 2dp+1
        pacc0 *= resc;
        pacc1 *= resc;
        {
            const float scp = (ph < 2) ? sc0 : sc1;   // node-half scale
            const char* xb = smem + XB_OFF + p * XBUF_SZ;
            #pragma unroll 4
            for (int i = 0; i < 16; ++i) {
                const int n = ph * 16 + i;
                const float ev = es[n] * scp;          // warp-broadcast LDS
                const uint32_t h2 = *(const uint32_t*)(xb + n * (KP * 2) + dp * 4);
                const float v0 =
                    __half2float(__ushort_as_half((unsigned short)(h2 & 0xffff)));
                const float v1 =
                    __half2float(__ushort_as_half((unsigned short)(h2 >> 16)));
                pacc0 = fmaf(ev, v0, pacc0);
                pacc1 = fmaf(ev, v1, pacc1);
            }
        }
    }

    // ---- combine node-quarter partials, write out
    __syncthreads();
    if (ph > 0) {
        acc2[(ph - 1) * IN_DIM + 2 * dp]     = pacc0;
        acc2[(ph - 1) * IN_DIM + 2 * dp + 1] = pacc1;
    }
    __syncthreads();
    if (ph == 0) {
        float2 o2 = make_float2(0.f, 0.f);
        if (end > start) {
            float s0 = pacc0, s1 = pacc1;
            #pragma unroll
            for (int q = 0; q < 3; ++q) {
                s0 += acc2[q * IN_DIM + 2 * dp];
                s1 += acc2[q * IN_DIM + 2 * dp + 1];
            }
            o2.x = s0 / s_run;
            o2.y = s1 / s_run;
        }
        *((float2*)(out + (size_t)g * IN_DIM) + dp) = o2;
    }
}

// ---------------------------------------------------------------------------
extern "C" void kernel_launch(void* const* d_in, const int* in_sizes, int n_in,
                              void* d_out, int out_size)
{
    const float* x   = (const float*)d_in[0];
    const int*   b32 = (const int*)d_in[1];   // int32 view: safe for i32/i64
    const float* W1  = (const float*)d_in[2];
    const float* b1  = (const float*)d_in[3];
    const float* W2  = (const float*)d_in[4];
    const float* b2  = (const float*)d_in[5];
    float*       out = (float*)d_out;

    const int N = in_sizes[0] / IN_DIM;
    int G = out_size / IN_DIM;
    if (G > G_MAX) G = G_MAX;

    seg_offsets_kernel<<<(N + 1 + 255) / 256, 256>>>(b32, N, G);

    cudaFuncSetAttribute(attn_pool_kernel,
                         cudaFuncAttributeMaxDynamicSharedMemorySize, SMEM_TOTAL);
    attn_pool_kernel<<<G, THREADS, SMEM_TOTAL>>>(x, W1, b1, W2, b2, out);
}